// round 14
// baseline (speedup 1.0000x reference)
#include <cuda_runtime.h>
#include <cuda_fp16.h>
#include <math.h>

#define N_USERS      100000
#define N_ITEMS      50000
#define N_ENTITIES   180000
#define N_USER_NODES 150000
#define N_REL        32
#define D            64
#define DV4          16   // D/4 float4 chunks per row

// ---------------- scratch (device globals; no allocation allowed) ----------
__device__ float g_eagg[(size_t)N_ENTITIES * D];
__device__ float g_aagg[(size_t)N_USER_NODES * D];
__device__ float g_iu  [(size_t)N_ITEMS * D];
__device__ float g_ui  [(size_t)N_USERS * D];
__device__ float g_cnt_e [N_ENTITIES];
__device__ float g_cnt_a [N_USER_NODES];
__device__ float g_cnt_iu[N_ITEMS];
__device__ float g_cnt_ui[N_USERS];

// fp16 copies of the embedding tables (42MB total -> mostly L2 resident)
__device__ uint2 g_eemb_h[(size_t)N_ENTITIES * DV4];
__device__ uint2 g_uemb_h[(size_t)N_USER_NODES * DV4];

__device__ __forceinline__ float4 mul4(float4 a, float4 b) {
    return make_float4(a.x * b.x, a.y * b.y, a.z * b.z, a.w * b.w);
}

__device__ __forceinline__ uint2 f4_to_h4(float4 v) {
    __half2 lo = __floats2half2_rn(v.x, v.y);
    __half2 hi = __floats2half2_rn(v.z, v.w);
    uint2 o;
    o.x = *reinterpret_cast<unsigned*>(&lo);
    o.y = *reinterpret_cast<unsigned*>(&hi);
    return o;
}

__device__ __forceinline__ float4 h4_to_f4(uint2 p) {
    __half2 lo = *reinterpret_cast<__half2*>(&p.x);
    __half2 hi = *reinterpret_cast<__half2*>(&p.y);
    float2 f0 = __half22float2(lo);
    float2 f1 = __half22float2(hi);
    return make_float4(f0.x, f0.y, f1.x, f1.y);
}

// ---------------- prep: zero accumulators + build fp16 tables --------------
__global__ void prep(const float4* __restrict__ eemb,
                     const float4* __restrict__ uemb, int zb)
{
    int b = blockIdx.x;
    if (b < zb) {
        int gid = b * 256 + threadIdx.x;
        int stride = zb * 256;
        float4 z = make_float4(0.f, 0.f, 0.f, 0.f);
#define ZLOOP(arr, n4) { float4* p = (float4*)(arr); \
        for (int i = gid; i < (n4); i += stride) p[i] = z; }
        ZLOOP(g_eagg, N_ENTITIES * DV4)
        ZLOOP(g_aagg, N_USER_NODES * DV4)
        ZLOOP(g_iu,   N_ITEMS * DV4)
        ZLOOP(g_ui,   N_USERS * DV4)
        ZLOOP(g_cnt_e,  N_ENTITIES / 4)
        ZLOOP(g_cnt_a,  N_USER_NODES / 4)
        ZLOOP(g_cnt_iu, N_ITEMS / 4)
        ZLOOP(g_cnt_ui, N_USERS / 4)
#undef ZLOOP
    } else {
        int nb = gridDim.x - zb;
        int gid = (b - zb) * 256 + threadIdx.x;
        int stride = nb * 256;
        const int nE = N_ENTITIES * DV4;
        const int nU = N_USER_NODES * DV4;
        for (int i = gid; i < nE; i += stride)
            g_eemb_h[i] = f4_to_h4(__ldg(eemb + i));
        for (int i = gid; i < nU; i += stride)
            g_uemb_h[i] = f4_to_h4(__ldg(uemb + i));
    }
}

// ---------------- typed scatter, 3-stage value pipeline --------------------
// Stage layout per iteration:
//   prefetch idx[i+2]  (independent)
//   issue gather v[i+1] (its idx was loaded one full iteration ago)
//   RED edge i          (its value was gathered one full iteration ago)
__device__ __forceinline__ void scatter_body_pl(
    const uint2* __restrict__ embh, const float4* __restrict__ sw,
    const int* __restrict__ head, const int* __restrict__ tail,
    const int* __restrict__ etype,
    float4* __restrict__ agg, float* __restrict__ cnt, int n_edges,
    int blk, int nblocks)
{
    int gid = blk * 256 + threadIdx.x;
    int c = gid & 15;
    int stride = nblocks * 256;
    int total = n_edges << 4;

    int g0 = gid;
    if (g0 >= total) return;
    int e0 = g0 >> 4;
    int h0  = __ldg(head + e0);
    int t0  = __ldg(tail + e0);
    int ty0 = __ldg(etype + e0);
    uint2 v0 = __ldg(embh + t0 * DV4 + c);

    int g1 = g0 + stride;
    bool m1 = g1 < total;
    int h1 = 0, t1 = 0, ty1 = 0;
    if (m1) {
        int e1 = g1 >> 4;
        h1  = __ldg(head + e1);
        t1  = __ldg(tail + e1);
        ty1 = __ldg(etype + e1);
    }

    while (true) {
        int g2 = g1 + stride;
        bool m2 = m1 && (g2 < total);
        int h2 = 0, t2 = 0, ty2 = 0;
        if (m2) {
            int e2 = g2 >> 4;
            h2  = __ldg(head + e2);
            t2  = __ldg(tail + e2);
            ty2 = __ldg(etype + e2);
        }
        uint2 v1 = make_uint2(0u, 0u);
        if (m1) v1 = __ldg(embh + t1 * DV4 + c);

        float4 vv = h4_to_f4(v0);
        float4 w  = sw[ty0 * DV4 + c];
        atomicAdd(agg + h0 * DV4 + c, mul4(vv, w));
        if (c == 0) atomicAdd(cnt + h0, 1.0f);

        if (!m1) break;
        h0 = h1; ty0 = ty1; v0 = v1;
        h1 = h2; t1 = t2; ty1 = ty2; m1 = m2; g1 = g2;
    }
}

// mat body: same pipeline, two gather->RED chains per edge
__device__ __forceinline__ void scatter_mat_pl(
    float4 w0, const int* __restrict__ mrow, const int* __restrict__ mcol,
    int n, int blk, int nblocks)
{
    int gid = blk * 256 + threadIdx.x;
    int c = gid & 15;
    int stride = nblocks * 256;
    float4* iu = (float4*)g_iu;
    float4* ui = (float4*)g_ui;
    int total = n << 4;

    int g0 = gid;
    if (g0 >= total) return;
    int e0 = g0 >> 4;
    int r0  = __ldg(mrow + e0);
    int cl0 = __ldg(mcol + e0);
    uint2 uv0 = __ldg(g_uemb_h + r0  * DV4 + c);
    uint2 ev0 = __ldg(g_eemb_h + cl0 * DV4 + c);

    int g1 = g0 + stride;
    bool m1 = g1 < total;
    int r1 = 0, cl1 = 0;
    if (m1) {
        int e1 = g1 >> 4;
        r1  = __ldg(mrow + e1);
        cl1 = __ldg(mcol + e1);
    }

    while (true) {
        int g2 = g1 + stride;
        bool m2 = m1 && (g2 < total);
        int r2 = 0, cl2 = 0;
        if (m2) {
            int e2 = g2 >> 4;
            r2  = __ldg(mrow + e2);
            cl2 = __ldg(mcol + e2);
        }
        uint2 uv1 = make_uint2(0u, 0u), ev1 = make_uint2(0u, 0u);
        if (m1) {
            uv1 = __ldg(g_uemb_h + r1  * DV4 + c);
            ev1 = __ldg(g_eemb_h + cl1 * DV4 + c);
        }

        atomicAdd(iu + cl0 * DV4 + c, mul4(h4_to_f4(uv0), w0));
        atomicAdd(ui + r0  * DV4 + c, mul4(h4_to_f4(ev0), w0));
        if (c == 0) {
            atomicAdd(g_cnt_iu + cl0, 1.0f);
            atomicAdd(g_cnt_ui + r0,  1.0f);
        }

        if (!m1) break;
        r0 = r1; cl0 = cl1; uv0 = uv1; ev0 = ev1;
        r1 = r2; cl1 = cl2; m1 = m2; g1 = g2;
    }
}

// ---------------- fused scatter: single persistent wave --------------------
__global__ void __launch_bounds__(256, 5)
scatter_all(const float4* __restrict__ weight,
            const int* __restrict__ e_head, const int* __restrict__ e_tail,
            const int* __restrict__ e_type, int n_e,
            const int* __restrict__ u_head, const int* __restrict__ u_tail,
            const int* __restrict__ u_type, int n_ue,
            const int* __restrict__ mrow, const int* __restrict__ mcol, int n_m,
            int b_e, int b_u)
{
    __shared__ float4 sw[N_REL * DV4];
    int b = blockIdx.x;
    if (b < b_u) {
        for (int i = threadIdx.x; i < N_REL * DV4; i += blockDim.x)
            sw[i] = __ldg(weight + i);
    }
    __syncthreads();

    if (b < b_e) {
        scatter_body_pl(g_eemb_h, sw, e_head, e_tail, e_type,
                        (float4*)g_eagg, g_cnt_e, n_e, b, b_e);
    } else if (b < b_u) {
        scatter_body_pl(g_uemb_h, sw, u_head, u_tail, u_type,
                        (float4*)g_aagg, g_cnt_a, n_ue, b - b_e, b_u - b_e);
    } else {
        float4 w0 = __ldg(weight + (threadIdx.x & 15));
        scatter_mat_pl(w0, mrow, mcol, n_m, b - b_u, gridDim.x - b_u);
    }
}

// ---------------- gated fusion, K-split two-stage ----------------------------
#define GPAD 68
#define GATE_SMEM ((2 * 64 * GPAD + 128) * 4)

__device__ __forceinline__ void gate_body(
    const float* __restrict__ aggA, const float* __restrict__ cntA,
    const float* __restrict__ aggB, const float* __restrict__ cntB,
    const float* __restrict__ GA,   const float* __restrict__ GB,
    float* __restrict__ out, int nrows, int blk, int mode)
{
    extern __shared__ float sm[];
    float* As   = sm;               // [64][GPAD] current-stage operand^T
    float* Gs   = sm + 64 * GPAD;   // [64][GPAD] current-stage gate^T
    float* invA = Gs + 64 * GPAD;   // [64]
    float* invB = invA + 64;        // [64]

    int tid = threadIdx.x;
    int row0 = blk * 64;

    if (tid < 64) {
        int r = row0 + tid;
        invA[tid] = (r < nrows) ? 1.f / fmaxf(__ldg(cntA + r), 1.f) : 0.f;
    } else if (tid < 128) {
        int r = row0 + tid - 64;
        invB[tid - 64] = (r < nrows) ? 1.f / fmaxf(__ldg(cntB + r), 1.f) : 0.f;
    }
    __syncthreads();

    int tx = tid & 15, ty = tid >> 4;
    const float4* As4 = (const float4*)As;
    const float4* Gs4 = (const float4*)Gs;
    float acc[4][4] = {};
    float ast[4][4];

    // ---- stage A ----
    for (int idx = tid; idx < 64 * 64; idx += 256) {
        int r = idx >> 6, k = idx & 63;
        int row = row0 + r;
        As[k * GPAD + r] = (row < nrows) ? aggA[(size_t)row * D + k] * invA[r] : 0.f;
    }
    for (int idx = tid; idx < 64 * 64; idx += 256) {
        int j = idx >> 6, k = idx & 63;
        Gs[k * GPAD + j] = __ldg(GA + idx);
    }
    __syncthreads();

#pragma unroll
    for (int j = 0; j < 4; j++) {
        float4 v = As4[(tx * 4 + j) * (GPAD / 4) + ty];
        ast[0][j] = v.x; ast[1][j] = v.y; ast[2][j] = v.z; ast[3][j] = v.w;
    }
#pragma unroll 4
    for (int k = 0; k < 64; k++) {
        float4 av = As4[k * (GPAD / 4) + ty];
        float4 gv = Gs4[k * (GPAD / 4) + tx];
        float a_[4] = {av.x, av.y, av.z, av.w};
        float g_[4] = {gv.x, gv.y, gv.z, gv.w};
#pragma unroll
        for (int i = 0; i < 4; i++)
#pragma unroll
            for (int j = 0; j < 4; j++)
                acc[i][j] += a_[i] * g_[j];
    }
    __syncthreads();

    // ---- stage B ----
    for (int idx = tid; idx < 64 * 64; idx += 256) {
        int r = idx >> 6, k = idx & 63;
        int row = row0 + r;
        As[k * GPAD + r] = (row < nrows) ? aggB[(size_t)row * D + k] * invB[r] : 0.f;
    }
    for (int idx = tid; idx < 64 * 64; idx += 256) {
        int j = idx >> 6, k = idx & 63;
        Gs[k * GPAD + j] = __ldg(GB + idx);
    }
    __syncthreads();

#pragma unroll 4
    for (int k = 0; k < 64; k++) {
        float4 av = As4[k * (GPAD / 4) + ty];
        float4 gv = Gs4[k * (GPAD / 4) + tx];
        float a_[4] = {av.x, av.y, av.z, av.w};
        float g_[4] = {gv.x, gv.y, gv.z, gv.w};
#pragma unroll
        for (int i = 0; i < 4; i++)
#pragma unroll
            for (int j = 0; j < 4; j++)
                acc[i][j] += a_[i] * g_[j];
    }

    // ---- blend + store ----
    float bst[4][4];
#pragma unroll
    for (int j = 0; j < 4; j++) {
        float4 v = As4[(tx * 4 + j) * (GPAD / 4) + ty];
        bst[0][j] = v.x; bst[1][j] = v.y; bst[2][j] = v.z; bst[3][j] = v.w;
    }
#pragma unroll
    for (int i = 0; i < 4; i++) {
        int r = ty * 4 + i;
        int row = row0 + r;
        if (row >= nrows) continue;
        float4 o;
        float* op = &o.x;
#pragma unroll
        for (int j = 0; j < 4; j++) {
            float gate = 1.f / (1.f + __expf(-acc[i][j]));
            float a = ast[i][j], b = bst[i][j];
            op[j] = mode ? (gate * b + (1.f - gate) * a)
                         : (gate * a + (1.f - gate) * b);
        }
        *(float4*)(out + (size_t)row * D + tx * 4) = o;
    }
}

// ---------------- fused epilogue: gate0 | gate1 | normalize tails ----------
__global__ void __launch_bounds__(256, 5)
epilogue(const float* __restrict__ g1, const float* __restrict__ g2,
         const float* __restrict__ g3,
         float* __restrict__ out, float* __restrict__ user_out,
         int nb0, int nb1)
{
    int b = blockIdx.x;
    if (b < nb0) {
        gate_body(g_eagg, g_cnt_e, g_iu, g_cnt_iu, g1, g2, out, N_ITEMS, b, 0);
    } else if (b < nb0 + nb1) {
        gate_body(g_ui, g_cnt_ui, g_aagg, g_cnt_a, g2, g3, user_out, N_USERS,
                  b - nb0, 1);
    } else {
        int nb = gridDim.x - nb0 - nb1;
        int gid = (b - nb0 - nb1) * 256 + threadIdx.x;
        int stride = nb * 256;
        const int nE = (N_ENTITIES - N_ITEMS) * DV4;        // 2,080,000
        const int nU = (N_USER_NODES - N_USERS) * DV4;      //   800,000
        for (int i = gid; i < nE + nU; i += stride) {
            const float* agg; const float* cnt; float* dst; int r; int c;
            if (i < nE) {
                r = N_ITEMS + (i >> 4); c = i & 15;
                agg = g_eagg; cnt = g_cnt_e; dst = out;
            } else {
                int k = i - nE;
                r = N_USERS + (k >> 4); c = k & 15;
                agg = g_aagg; cnt = g_cnt_a; dst = user_out;
            }
            float ic = 1.f / fmaxf(__ldg(cnt + r), 1.f);
            float4 v = ((const float4*)agg)[(size_t)r * DV4 + c];
            ((float4*)dst)[(size_t)r * DV4 + c] =
                make_float4(v.x * ic, v.y * ic, v.z * ic, v.w * ic);
        }
    }
}

// ---------------- launch -----------------------------------------------------
extern "C" void kernel_launch(void* const* d_in, const int* in_sizes, int n_in,
                              void* d_out, int out_size)
{
    const float* entity_emb = (const float*)d_in[0];
    const float* user_emb   = (const float*)d_in[1];
    const float* weight     = (const float*)d_in[2];
    const float* gate1_w    = (const float*)d_in[3];
    const float* gate2_w    = (const float*)d_in[4];
    const float* gate3_w    = (const float*)d_in[5];
    const int*   edge_index = (const int*)d_in[6];
    const int*   edge_type  = (const int*)d_in[7];
    const int*   uedge_index= (const int*)d_in[8];
    const int*   uedge_type = (const int*)d_in[9];
    const int*   mat_row    = (const int*)d_in[10];
    const int*   mat_col    = (const int*)d_in[11];

    int n_e  = in_sizes[7];    // 1,500,000
    int n_ue = in_sizes[9];    // 1,000,000
    int n_m  = in_sizes[10];   // 1,500,000

    float* out = (float*)d_out;
    float* user_out = out + (size_t)N_ENTITIES * D;

    cudaFuncSetAttribute(epilogue, cudaFuncAttributeMaxDynamicSharedMemorySize, GATE_SMEM);

    // zero (123MB writes) + fp16 table build (126MB traffic), traffic-balanced
    prep<<<4096, 256>>>((const float4*)entity_emb, (const float4*)user_emb, 2008);

    // Single persistent wave: 5 blocks/SM x 148 SMs.
    // Partition by L2-traffic share (fp16 gathers):
    //   kg edge:  128B gather + 256B RED + 12B idx = 396B
    //   mat edge: 256B gather + 512B RED + 8B idx  = 776B
    const int SG = 740;
    double t_e = (double)n_e * 396.0;
    double t_u = (double)n_ue * 396.0;
    double t_m = (double)n_m * 776.0;
    double tot = t_e + t_u + t_m;
    int b_e = (int)(SG * (t_e / tot) + 0.5);
    int b_u = b_e + (int)(SG * (t_u / tot) + 0.5);
    if (b_e < 1) b_e = 1;
    if (b_u <= b_e) b_u = b_e + 1;
    if (b_u >= SG) b_u = SG - 1;

    scatter_all<<<SG, 256>>>((const float4*)weight,
                             edge_index, edge_index + n_e, edge_type, n_e,
                             uedge_index, uedge_index + n_ue, uedge_type, n_ue,
                             mat_row, mat_col, n_m,
                             b_e, b_u);

    int nb0 = (N_ITEMS + 63) / 64;   // 782
    int nb1 = (N_USERS + 63) / 64;   // 1563
    int nbn = 1024;                  // normalize partition (grid-stride)
    epilogue<<<nb0 + nb1 + nbn, 256, GATE_SMEM>>>(gate1_w, gate2_w, gate3_w,
                                                  out, user_out, nb0, nb1);
}

// round 15
// speedup vs baseline: 1.2649x; 1.2649x over previous
#include <cuda_runtime.h>
#include <cuda_fp16.h>
#include <math.h>

#define N_USERS      100000
#define N_ITEMS      50000
#define N_ENTITIES   180000
#define N_USER_NODES 150000
#define N_REL        32
#define D            64
#define DV4          16   // D/4 float4 chunks per row

// ---------------- scratch (device globals; no allocation allowed) ----------
__device__ float g_eagg[(size_t)N_ENTITIES * D];
__device__ float g_aagg[(size_t)N_USER_NODES * D];
__device__ float g_iu  [(size_t)N_ITEMS * D];
__device__ float g_ui  [(size_t)N_USERS * D];
__device__ float g_cnt_e [N_ENTITIES];
__device__ float g_cnt_a [N_USER_NODES];
__device__ float g_cnt_iu[N_ITEMS];
__device__ float g_cnt_ui[N_USERS];

// fp16 copies of the embedding tables (42MB total -> mostly L2 resident)
__device__ uint2 g_eemb_h[(size_t)N_ENTITIES * DV4];
__device__ uint2 g_uemb_h[(size_t)N_USER_NODES * DV4];

__device__ __forceinline__ float4 mul4(float4 a, float4 b) {
    return make_float4(a.x * b.x, a.y * b.y, a.z * b.z, a.w * b.w);
}

__device__ __forceinline__ uint2 f4_to_h4(float4 v) {
    __half2 lo = __floats2half2_rn(v.x, v.y);
    __half2 hi = __floats2half2_rn(v.z, v.w);
    uint2 o;
    o.x = *reinterpret_cast<unsigned*>(&lo);
    o.y = *reinterpret_cast<unsigned*>(&hi);
    return o;
}

__device__ __forceinline__ float4 h4_to_f4(uint2 p) {
    __half2 lo = *reinterpret_cast<__half2*>(&p.x);
    __half2 hi = *reinterpret_cast<__half2*>(&p.y);
    float2 f0 = __half22float2(lo);
    float2 f1 = __half22float2(hi);
    return make_float4(f0.x, f0.y, f1.x, f1.y);
}

// streaming (evict-first) int load: keeps one-shot index streams from
// displacing the fp16 gather tables in L2
__device__ __forceinline__ int ldcs_i(const int* p) { return __ldcs(p); }

// ---------------- prep: zero accumulators + build fp16 tables --------------
__global__ void prep(const float4* __restrict__ eemb,
                     const float4* __restrict__ uemb, int zb)
{
    int b = blockIdx.x;
    if (b < zb) {
        int gid = b * 256 + threadIdx.x;
        int stride = zb * 256;
        float4 z = make_float4(0.f, 0.f, 0.f, 0.f);
#define ZLOOP(arr, n4) { float4* p = (float4*)(arr); \
        for (int i = gid; i < (n4); i += stride) p[i] = z; }
        ZLOOP(g_eagg, N_ENTITIES * DV4)
        ZLOOP(g_aagg, N_USER_NODES * DV4)
        ZLOOP(g_iu,   N_ITEMS * DV4)
        ZLOOP(g_ui,   N_USERS * DV4)
        ZLOOP(g_cnt_e,  N_ENTITIES / 4)
        ZLOOP(g_cnt_a,  N_USER_NODES / 4)
        ZLOOP(g_cnt_iu, N_ITEMS / 4)
        ZLOOP(g_cnt_ui, N_USERS / 4)
#undef ZLOOP
    } else {
        int nb = gridDim.x - zb;
        int gid = (b - zb) * 256 + threadIdx.x;
        int stride = nb * 256;
        const int nE = N_ENTITIES * DV4;
        const int nU = N_USER_NODES * DV4;
        for (int i = gid; i < nE; i += stride)
            g_eemb_h[i] = f4_to_h4(__ldg(eemb + i));
        for (int i = gid; i < nU; i += stride)
            g_uemb_h[i] = f4_to_h4(__ldg(uemb + i));
    }
}

// ---------------- typed scatter body (index-prefetch, fp16 gathers) --------
// R13-exact structure: idx for iteration i+1 prefetched before the gather of
// iteration i. Idx loads are streaming (__ldcs).
__device__ __forceinline__ void scatter_body_pf(
    const uint2* __restrict__ embh, const float4* __restrict__ sw,
    const int* __restrict__ head, const int* __restrict__ tail,
    const int* __restrict__ etype,
    float4* __restrict__ agg, float* __restrict__ cnt, int n_edges,
    int blk, int nblocks)
{
    int gid = blk * 256 + threadIdx.x;
    int c = gid & 15;
    int stride = nblocks * 256;
    int total = n_edges << 4;

    int g = gid;
    if (g >= total) return;
    int e = g >> 4;
    int h  = ldcs_i(head + e);
    int t  = ldcs_i(tail + e);
    int ty = ldcs_i(etype + e);

    while (true) {
        int gn = g + stride;
        bool more = gn < total;
        int hn = 0, tn = 0, tyn = 0;
        if (more) {
            int en = gn >> 4;
            hn  = ldcs_i(head + en);
            tn  = ldcs_i(tail + en);
            tyn = ldcs_i(etype + en);
        }
        float4 v = h4_to_f4(__ldg(embh + t * DV4 + c));
        float4 w = sw[ty * DV4 + c];
        atomicAdd(agg + h * DV4 + c, mul4(v, w));
        if (c == 0) atomicAdd(cnt + h, 1.0f);
        if (!more) break;
        g = gn; h = hn; t = tn; ty = tyn;
    }
}

__device__ __forceinline__ void scatter_mat_body(
    float4 w0, const int* __restrict__ mrow, const int* __restrict__ mcol,
    int n, int blk, int nblocks)
{
    int gid = blk * 256 + threadIdx.x;
    int c = gid & 15;
    int stride = nblocks * 256;
    float4* iu = (float4*)g_iu;
    float4* ui = (float4*)g_ui;
    int total = n << 4;

    int g = gid;
    if (g >= total) return;
    int e = g >> 4;
    int r  = ldcs_i(mrow + e);
    int cl = ldcs_i(mcol + e);

    while (true) {
        int gn = g + stride;
        bool more = gn < total;
        int rn = 0, cln = 0;
        if (more) {
            int en = gn >> 4;
            rn  = ldcs_i(mrow + en);
            cln = ldcs_i(mcol + en);
        }
        float4 uv = h4_to_f4(__ldg(g_uemb_h + r  * DV4 + c));
        float4 ev = h4_to_f4(__ldg(g_eemb_h + cl * DV4 + c));
        atomicAdd(iu + cl * DV4 + c, mul4(uv, w0));
        atomicAdd(ui + r  * DV4 + c, mul4(ev, w0));
        if (c == 0) {
            atomicAdd(g_cnt_iu + cl, 1.0f);
            atomicAdd(g_cnt_ui + r,  1.0f);
        }
        if (!more) break;
        g = gn; r = rn; cl = cln;
    }
}

// ---------------- fused scatter: all three workloads, multi-wave grid ------
__global__ void __launch_bounds__(256, 8)
scatter_all(const float4* __restrict__ weight,
            const int* __restrict__ e_head, const int* __restrict__ e_tail,
            const int* __restrict__ e_type, int n_e,
            const int* __restrict__ u_head, const int* __restrict__ u_tail,
            const int* __restrict__ u_type, int n_ue,
            const int* __restrict__ mrow, const int* __restrict__ mcol, int n_m,
            int b_e, int b_u)
{
    __shared__ float4 sw[N_REL * DV4];
    int b = blockIdx.x;
    if (b < b_u) {
        for (int i = threadIdx.x; i < N_REL * DV4; i += blockDim.x)
            sw[i] = __ldg(weight + i);
    }
    __syncthreads();

    if (b < b_e) {
        scatter_body_pf(g_eemb_h, sw, e_head, e_tail, e_type,
                        (float4*)g_eagg, g_cnt_e, n_e, b, b_e);
    } else if (b < b_u) {
        scatter_body_pf(g_uemb_h, sw, u_head, u_tail, u_type,
                        (float4*)g_aagg, g_cnt_a, n_ue, b - b_e, b_u - b_e);
    } else {
        float4 w0 = __ldg(weight + (threadIdx.x & 15));
        scatter_mat_body(w0, mrow, mcol, n_m, b - b_u, gridDim.x - b_u);
    }
}

// ---------------- gated fusion, K-split two-stage ----------------------------
#define GPAD 68
#define GATE_SMEM ((2 * 64 * GPAD + 128) * 4)

__device__ __forceinline__ void gate_body(
    const float* __restrict__ aggA, const float* __restrict__ cntA,
    const float* __restrict__ aggB, const float* __restrict__ cntB,
    const float* __restrict__ GA,   const float* __restrict__ GB,
    float* __restrict__ out, int nrows, int blk, int mode)
{
    extern __shared__ float sm[];
    float* As   = sm;               // [64][GPAD] current-stage operand^T
    float* Gs   = sm + 64 * GPAD;   // [64][GPAD] current-stage gate^T
    float* invA = Gs + 64 * GPAD;   // [64]
    float* invB = invA + 64;        // [64]

    int tid = threadIdx.x;
    int row0 = blk * 64;

    if (tid < 64) {
        int r = row0 + tid;
        invA[tid] = (r < nrows) ? 1.f / fmaxf(__ldg(cntA + r), 1.f) : 0.f;
    } else if (tid < 128) {
        int r = row0 + tid - 64;
        invB[tid - 64] = (r < nrows) ? 1.f / fmaxf(__ldg(cntB + r), 1.f) : 0.f;
    }
    __syncthreads();

    int tx = tid & 15, ty = tid >> 4;
    const float4* As4 = (const float4*)As;
    const float4* Gs4 = (const float4*)Gs;
    float acc[4][4] = {};
    float ast[4][4];

    // ---- stage A ----
    for (int idx = tid; idx < 64 * 64; idx += 256) {
        int r = idx >> 6, k = idx & 63;
        int row = row0 + r;
        As[k * GPAD + r] = (row < nrows) ? aggA[(size_t)row * D + k] * invA[r] : 0.f;
    }
    for (int idx = tid; idx < 64 * 64; idx += 256) {
        int j = idx >> 6, k = idx & 63;
        Gs[k * GPAD + j] = __ldg(GA + idx);
    }
    __syncthreads();

#pragma unroll
    for (int j = 0; j < 4; j++) {
        float4 v = As4[(tx * 4 + j) * (GPAD / 4) + ty];
        ast[0][j] = v.x; ast[1][j] = v.y; ast[2][j] = v.z; ast[3][j] = v.w;
    }
#pragma unroll 4
    for (int k = 0; k < 64; k++) {
        float4 av = As4[k * (GPAD / 4) + ty];
        float4 gv = Gs4[k * (GPAD / 4) + tx];
        float a_[4] = {av.x, av.y, av.z, av.w};
        float g_[4] = {gv.x, gv.y, gv.z, gv.w};
#pragma unroll
        for (int i = 0; i < 4; i++)
#pragma unroll
            for (int j = 0; j < 4; j++)
                acc[i][j] += a_[i] * g_[j];
    }
    __syncthreads();

    // ---- stage B ----
    for (int idx = tid; idx < 64 * 64; idx += 256) {
        int r = idx >> 6, k = idx & 63;
        int row = row0 + r;
        As[k * GPAD + r] = (row < nrows) ? aggB[(size_t)row * D + k] * invB[r] : 0.f;
    }
    for (int idx = tid; idx < 64 * 64; idx += 256) {
        int j = idx >> 6, k = idx & 63;
        Gs[k * GPAD + j] = __ldg(GB + idx);
    }
    __syncthreads();

#pragma unroll 4
    for (int k = 0; k < 64; k++) {
        float4 av = As4[k * (GPAD / 4) + ty];
        float4 gv = Gs4[k * (GPAD / 4) + tx];
        float a_[4] = {av.x, av.y, av.z, av.w};
        float g_[4] = {gv.x, gv.y, gv.z, gv.w};
#pragma unroll
        for (int i = 0; i < 4; i++)
#pragma unroll
            for (int j = 0; j < 4; j++)
                acc[i][j] += a_[i] * g_[j];
    }

    // ---- blend + store ----
    float bst[4][4];
#pragma unroll
    for (int j = 0; j < 4; j++) {
        float4 v = As4[(tx * 4 + j) * (GPAD / 4) + ty];
        bst[0][j] = v.x; bst[1][j] = v.y; bst[2][j] = v.z; bst[3][j] = v.w;
    }
#pragma unroll
    for (int i = 0; i < 4; i++) {
        int r = ty * 4 + i;
        int row = row0 + r;
        if (row >= nrows) continue;
        float4 o;
        float* op = &o.x;
#pragma unroll
        for (int j = 0; j < 4; j++) {
            float gate = 1.f / (1.f + __expf(-acc[i][j]));
            float a = ast[i][j], b = bst[i][j];
            op[j] = mode ? (gate * b + (1.f - gate) * a)
                         : (gate * a + (1.f - gate) * b);
        }
        *(float4*)(out + (size_t)row * D + tx * 4) = o;
    }
}

// ---------------- fused epilogue: gate0 | gate1 | normalize tails ----------
__global__ void __launch_bounds__(256, 5)
epilogue(const float* __restrict__ g1, const float* __restrict__ g2,
         const float* __restrict__ g3,
         float* __restrict__ out, float* __restrict__ user_out,
         int nb0, int nb1)
{
    int b = blockIdx.x;
    if (b < nb0) {
        gate_body(g_eagg, g_cnt_e, g_iu, g_cnt_iu, g1, g2, out, N_ITEMS, b, 0);
    } else if (b < nb0 + nb1) {
        gate_body(g_ui, g_cnt_ui, g_aagg, g_cnt_a, g2, g3, user_out, N_USERS,
                  b - nb0, 1);
    } else {
        int nb = gridDim.x - nb0 - nb1;
        int gid = (b - nb0 - nb1) * 256 + threadIdx.x;
        int stride = nb * 256;
        const int nE = (N_ENTITIES - N_ITEMS) * DV4;        // 2,080,000
        const int nU = (N_USER_NODES - N_USERS) * DV4;      //   800,000
        for (int i = gid; i < nE + nU; i += stride) {
            const float* agg; const float* cnt; float* dst; int r; int c;
            if (i < nE) {
                r = N_ITEMS + (i >> 4); c = i & 15;
                agg = g_eagg; cnt = g_cnt_e; dst = out;
            } else {
                int k = i - nE;
                r = N_USERS + (k >> 4); c = k & 15;
                agg = g_aagg; cnt = g_cnt_a; dst = user_out;
            }
            float ic = 1.f / fmaxf(__ldg(cnt + r), 1.f);
            float4 v = ((const float4*)agg)[(size_t)r * DV4 + c];
            ((float4*)dst)[(size_t)r * DV4 + c] =
                make_float4(v.x * ic, v.y * ic, v.z * ic, v.w * ic);
        }
    }
}

// ---------------- launch -----------------------------------------------------
extern "C" void kernel_launch(void* const* d_in, const int* in_sizes, int n_in,
                              void* d_out, int out_size)
{
    const float* entity_emb = (const float*)d_in[0];
    const float* user_emb   = (const float*)d_in[1];
    const float* weight     = (const float*)d_in[2];
    const float* gate1_w    = (const float*)d_in[3];
    const float* gate2_w    = (const float*)d_in[4];
    const float* gate3_w    = (const float*)d_in[5];
    const int*   edge_index = (const int*)d_in[6];
    const int*   edge_type  = (const int*)d_in[7];
    const int*   uedge_index= (const int*)d_in[8];
    const int*   uedge_type = (const int*)d_in[9];
    const int*   mat_row    = (const int*)d_in[10];
    const int*   mat_col    = (const int*)d_in[11];

    int n_e  = in_sizes[7];    // 1,500,000
    int n_ue = in_sizes[9];    // 1,000,000
    int n_m  = in_sizes[10];   // 1,500,000

    float* out = (float*)d_out;
    float* user_out = out + (size_t)N_ENTITIES * D;

    cudaFuncSetAttribute(epilogue, cudaFuncAttributeMaxDynamicSharedMemorySize, GATE_SMEM);

    // zero (123MB writes) + fp16 table build (126MB traffic), traffic-balanced
    prep<<<4096, 256>>>((const float4*)entity_emb, (const float4*)user_emb, 2008);

    // Multi-wave grid (4 waves @ 8 blocks/SM) -> dynamic inter-partition balance.
    // Partition by L2-traffic share (fp16 gathers):
    //   kg edge:  128B gather + 256B RED + 12B idx = 396B
    //   mat edge: 256B gather + 512B RED + 8B idx  = 776B
    const int SG = 4736;
    double t_e = (double)n_e * 396.0;
    double t_u = (double)n_ue * 396.0;
    double t_m = (double)n_m * 776.0;
    double tot = t_e + t_u + t_m;
    int b_e = (int)(SG * (t_e / tot) + 0.5);
    int b_u = b_e + (int)(SG * (t_u / tot) + 0.5);
    if (b_e < 1) b_e = 1;
    if (b_u <= b_e) b_u = b_e + 1;
    if (b_u >= SG) b_u = SG - 1;

    scatter_all<<<SG, 256>>>((const float4*)weight,
                             edge_index, edge_index + n_e, edge_type, n_e,
                             uedge_index, uedge_index + n_ue, uedge_type, n_ue,
                             mat_row, mat_col, n_m,
                             b_e, b_u);

    int nb0 = (N_ITEMS + 63) / 64;   // 782
    int nb1 = (N_USERS + 63) / 64;   // 1563
    int nbn = 1024;                  // normalize partition (grid-stride)
    epilogue<<<nb0 + nb1 + nbn, 256, GATE_SMEM>>>(gate1_w, gate2_w, gate3_w,
                                                  out, user_out, nb0, nb1);
}

// round 16
// speedup vs baseline: 1.3767x; 1.0884x over previous
#include <cuda_runtime.h>
#include <cuda_fp16.h>
#include <math.h>

#define N_USERS      100000
#define N_ITEMS      50000
#define N_ENTITIES   180000
#define N_USER_NODES 150000
#define N_REL        32
#define D            64
#define DV4          16   // D/4 float4 chunks per row

// virtual destination-row space: [E | A | IU | UI]
#define A_BASE  N_ENTITIES                   // 180000
#define IU_BASE (A_BASE + N_USER_NODES)      // 330000
#define UI_BASE (IU_BASE + N_ITEMS)          // 380000
#define NTOT    (UI_BASE + N_USERS)          // 480000  (= 1875 * 256 exactly)
#define NB_SCAN (NTOT / 256)                 // 1875
#define POST_MAX 6000000

// ---------------- scratch (device globals; no allocation allowed) ----------
// mean outputs consumed by the gate epilogue (tails go straight to d_out)
__device__ float g_eagg[(size_t)N_ITEMS * D];
__device__ float g_aagg[(size_t)N_USERS * D];
__device__ float g_iu  [(size_t)N_ITEMS * D];
__device__ float g_ui  [(size_t)N_USERS * D];

// fp16 copies of the embedding tables (21MB -> L2 resident)
__device__ uint2 g_eemb_h[(size_t)N_ENTITIES * DV4];
__device__ uint2 g_uemb_h[(size_t)N_USER_NODES * DV4];

// CSR machinery
__device__ int g_deg [NTOT];
__device__ int g_off [NTOT + 1];
__device__ int g_cur [NTOT];
__device__ int g_bsum[NB_SCAN];
__device__ int g_post[POST_MAX];   // posting = src | (type << 20)

__device__ __forceinline__ uint2 f4_to_h4(float4 v) {
    __half2 lo = __floats2half2_rn(v.x, v.y);
    __half2 hi = __floats2half2_rn(v.z, v.w);
    uint2 o;
    o.x = *reinterpret_cast<unsigned*>(&lo);
    o.y = *reinterpret_cast<unsigned*>(&hi);
    return o;
}

__device__ __forceinline__ float4 h4_to_f4(uint2 p) {
    __half2 lo = *reinterpret_cast<__half2*>(&p.x);
    __half2 hi = *reinterpret_cast<__half2*>(&p.y);
    float2 f0 = __half22float2(lo);
    float2 f1 = __half22float2(hi);
    return make_float4(f0.x, f0.y, f1.x, f1.y);
}

// ---------------- prep: zero degree array + build fp16 tables ---------------
__global__ void prep(const float4* __restrict__ eemb,
                     const float4* __restrict__ uemb)
{
    int gid = blockIdx.x * 256 + threadIdx.x;
    int stride = gridDim.x * 256;
    for (int i = gid; i < NTOT; i += stride) g_deg[i] = 0;
    const int nE = N_ENTITIES * DV4, nU = N_USER_NODES * DV4;
    for (int i = gid; i < nE; i += stride) g_eemb_h[i] = f4_to_h4(__ldg(eemb + i));
    for (int i = gid; i < nU; i += stride) g_uemb_h[i] = f4_to_h4(__ldg(uemb + i));
}

// ---------------- pass 1: histogram of destination degrees ------------------
__global__ void hist(const int* __restrict__ e_head, int n_e,
                     const int* __restrict__ u_head, int n_ue,
                     const int* __restrict__ mrow,
                     const int* __restrict__ mcol, int n_m)
{
    int stride = gridDim.x * 256;
    int n01 = n_e + n_ue, n012 = n01 + n_m, nall = n012 + n_m;
    for (int i = blockIdx.x * 256 + threadIdx.x; i < nall; i += stride) {
        int dest;
        if      (i < n_e)  dest = __ldcs(e_head + i);
        else if (i < n01)  dest = A_BASE  + __ldcs(u_head + (i - n_e));
        else if (i < n012) dest = IU_BASE + __ldcs(mcol + (i - n01));
        else               dest = UI_BASE + __ldcs(mrow + (i - n012));
        atomicAdd(&g_deg[dest], 1);
    }
}

// ---------------- pass 2: exclusive scan (3 tiny kernels) -------------------
__global__ void scan1()
{
    __shared__ int s[256];
    int i = blockIdx.x * 256 + threadIdx.x;     // NTOT = 1875*256 exactly
    int v = g_deg[i];
    s[threadIdx.x] = v;
    __syncthreads();
#pragma unroll
    for (int d = 1; d < 256; d <<= 1) {
        int t = (threadIdx.x >= d) ? s[threadIdx.x - d] : 0;
        __syncthreads();
        s[threadIdx.x] += t;
        __syncthreads();
    }
    g_off[i] = s[threadIdx.x] - v;              // exclusive within block
    if (threadIdx.x == 255) g_bsum[blockIdx.x] = s[255];
}

__global__ void scan2()   // single block: exclusive scan of block sums
{
    __shared__ int s[256];
    __shared__ int carry_s;
    if (threadIdx.x == 0) carry_s = 0;
    __syncthreads();
    for (int base = 0; base < NB_SCAN; base += 256) {
        int i = base + threadIdx.x;
        int v = (i < NB_SCAN) ? g_bsum[i] : 0;
        s[threadIdx.x] = v;
        __syncthreads();
#pragma unroll
        for (int d = 1; d < 256; d <<= 1) {
            int t = (threadIdx.x >= d) ? s[threadIdx.x - d] : 0;
            __syncthreads();
            s[threadIdx.x] += t;
            __syncthreads();
        }
        if (i < NB_SCAN) g_bsum[i] = s[threadIdx.x] - v + carry_s;
        __syncthreads();
        if (threadIdx.x == 0) carry_s += s[255];
        __syncthreads();
    }
}

__global__ void scan3(int n_all)
{
    int i = blockIdx.x * 256 + threadIdx.x;
    int v = g_off[i] + g_bsum[blockIdx.x];
    g_off[i] = v;
    g_cur[i] = v;
    if (i == 0) g_off[NTOT] = n_all;
}

// ---------------- pass 3: fill postings --------------------------------------
__global__ void fill(const int* __restrict__ e_head, const int* __restrict__ e_tail,
                     const int* __restrict__ e_type, int n_e,
                     const int* __restrict__ u_head, const int* __restrict__ u_tail,
                     const int* __restrict__ u_type, int n_ue,
                     const int* __restrict__ mrow,
                     const int* __restrict__ mcol, int n_m)
{
    int stride = gridDim.x * 256;
    int n01 = n_e + n_ue, n012 = n01 + n_m, nall = n012 + n_m;
    for (int i = blockIdx.x * 256 + threadIdx.x; i < nall; i += stride) {
        int dest, pk;
        if (i < n_e) {
            dest = __ldcs(e_head + i);
            pk   = __ldcs(e_tail + i) | (__ldcs(e_type + i) << 20);
        } else if (i < n01) {
            int j = i - n_e;
            dest = A_BASE + __ldcs(u_head + j);
            pk   = __ldcs(u_tail + j) | (__ldcs(u_type + j) << 20);
        } else if (i < n012) {
            int j = i - n01;
            dest = IU_BASE + __ldcs(mcol + j);
            pk   = __ldcs(mrow + j);                    // type 0 == weight[0]
        } else {
            int j = i - n012;
            dest = UI_BASE + __ldcs(mrow + j);
            pk   = __ldcs(mcol + j);                    // type 0 == weight[0]
        }
        int pos = atomicAdd(&g_cur[dest], 1);
        g_post[pos] = pk;
    }
}

// ---------------- pass 4: gather (NO atomics) --------------------------------
// One warp per destination row: lanes 0-15 = 16 chunks of even postings,
// lanes 16-31 = 16 chunks of odd postings; halves combined by shfl_xor(16).
// Writes the MEAN directly; tail rows go straight to d_out.
__global__ void __launch_bounds__(256, 8)
gather(const float4* __restrict__ weight,
       float* __restrict__ out, float* __restrict__ user_out)
{
    __shared__ float4 sw[N_REL * DV4];
    for (int i = threadIdx.x; i < N_REL * DV4; i += 256)
        sw[i] = __ldg(weight + i);
    __syncthreads();

    int lane = threadIdx.x & 31;
    int c = lane & 15, half = lane >> 4;
    int warp_id = (blockIdx.x * 256 + threadIdx.x) >> 5;
    int nwarps = (gridDim.x * 256) >> 5;

    for (int vr = warp_id; vr < NTOT; vr += nwarps) {
        int p0 = g_off[vr], p1 = g_off[vr + 1];
        const uint2* tab = (vr < A_BASE)  ? g_eemb_h
                         : (vr < UI_BASE) ? g_uemb_h     // A and IU both gather users
                                          : g_eemb_h;    // UI gathers entities

        float4 acc = make_float4(0.f, 0.f, 0.f, 0.f);
        for (int p = p0 + half; p < p1; p += 2) {
            int e = __ldg((const int*)g_post + p);
            int src = e & 0xFFFFF, ty = e >> 20;
            float4 v = h4_to_f4(__ldg(tab + src * DV4 + c));
            float4 w = sw[ty * DV4 + c];
            acc.x += v.x * w.x; acc.y += v.y * w.y;
            acc.z += v.z * w.z; acc.w += v.w * w.w;
        }
        acc.x += __shfl_xor_sync(0xffffffff, acc.x, 16);
        acc.y += __shfl_xor_sync(0xffffffff, acc.y, 16);
        acc.z += __shfl_xor_sync(0xffffffff, acc.z, 16);
        acc.w += __shfl_xor_sync(0xffffffff, acc.w, 16);

        if (half == 0) {
            float inv = 1.f / fmaxf((float)(p1 - p0), 1.f);
            float4 m = make_float4(acc.x * inv, acc.y * inv, acc.z * inv, acc.w * inv);
            float4* dst;
            if (vr < A_BASE) {
                int r = vr;
                dst = (r < N_ITEMS) ? (float4*)g_eagg + (size_t)r * DV4
                                    : (float4*)out    + (size_t)r * DV4;
            } else if (vr < IU_BASE) {
                int r = vr - A_BASE;
                dst = (r < N_USERS) ? (float4*)g_aagg   + (size_t)r * DV4
                                    : (float4*)user_out + (size_t)r * DV4;
            } else if (vr < UI_BASE) {
                dst = (float4*)g_iu + (size_t)(vr - IU_BASE) * DV4;
            } else {
                dst = (float4*)g_ui + (size_t)(vr - UI_BASE) * DV4;
            }
            dst[c] = m;
        }
    }
}

// ---------------- gated fusion (inputs are already means) --------------------
#define GPAD 68
#define GATE_SMEM ((2 * 64 * GPAD) * 4)

__device__ __forceinline__ void gate_body(
    const float* __restrict__ aggA, const float* __restrict__ aggB,
    const float* __restrict__ GA,   const float* __restrict__ GB,
    float* __restrict__ out, int nrows, int blk, int mode)
{
    extern __shared__ float sm[];
    float* As = sm;                 // [64][GPAD] current-stage operand^T
    float* Gs = sm + 64 * GPAD;     // [64][GPAD] current-stage gate^T

    int tid = threadIdx.x;
    int row0 = blk * 64;
    int tx = tid & 15, ty = tid >> 4;
    const float4* As4 = (const float4*)As;
    const float4* Gs4 = (const float4*)Gs;
    float acc[4][4] = {};
    float ast[4][4];

    // ---- stage A ----
    for (int idx = tid; idx < 64 * 64; idx += 256) {
        int r = idx >> 6, k = idx & 63;
        int row = row0 + r;
        As[k * GPAD + r] = (row < nrows) ? aggA[(size_t)row * D + k] : 0.f;
    }
    for (int idx = tid; idx < 64 * 64; idx += 256) {
        int j = idx >> 6, k = idx & 63;
        Gs[k * GPAD + j] = __ldg(GA + idx);
    }
    __syncthreads();

#pragma unroll
    for (int j = 0; j < 4; j++) {
        float4 v = As4[(tx * 4 + j) * (GPAD / 4) + ty];
        ast[0][j] = v.x; ast[1][j] = v.y; ast[2][j] = v.z; ast[3][j] = v.w;
    }
#pragma unroll 4
    for (int k = 0; k < 64; k++) {
        float4 av = As4[k * (GPAD / 4) + ty];
        float4 gv = Gs4[k * (GPAD / 4) + tx];
        float a_[4] = {av.x, av.y, av.z, av.w};
        float g_[4] = {gv.x, gv.y, gv.z, gv.w};
#pragma unroll
        for (int i = 0; i < 4; i++)
#pragma unroll
            for (int j = 0; j < 4; j++)
                acc[i][j] += a_[i] * g_[j];
    }
    __syncthreads();

    // ---- stage B ----
    for (int idx = tid; idx < 64 * 64; idx += 256) {
        int r = idx >> 6, k = idx & 63;
        int row = row0 + r;
        As[k * GPAD + r] = (row < nrows) ? aggB[(size_t)row * D + k] : 0.f;
    }
    for (int idx = tid; idx < 64 * 64; idx += 256) {
        int j = idx >> 6, k = idx & 63;
        Gs[k * GPAD + j] = __ldg(GB + idx);
    }
    __syncthreads();

#pragma unroll 4
    for (int k = 0; k < 64; k++) {
        float4 av = As4[k * (GPAD / 4) + ty];
        float4 gv = Gs4[k * (GPAD / 4) + tx];
        float a_[4] = {av.x, av.y, av.z, av.w};
        float g_[4] = {gv.x, gv.y, gv.z, gv.w};
#pragma unroll
        for (int i = 0; i < 4; i++)
#pragma unroll
            for (int j = 0; j < 4; j++)
                acc[i][j] += a_[i] * g_[j];
    }

    // ---- blend + store (B still resident in As) ----
    float bst[4][4];
#pragma unroll
    for (int j = 0; j < 4; j++) {
        float4 v = As4[(tx * 4 + j) * (GPAD / 4) + ty];
        bst[0][j] = v.x; bst[1][j] = v.y; bst[2][j] = v.z; bst[3][j] = v.w;
    }
#pragma unroll
    for (int i = 0; i < 4; i++) {
        int r = ty * 4 + i;
        int row = row0 + r;
        if (row >= nrows) continue;
        float4 o;
        float* op = &o.x;
#pragma unroll
        for (int j = 0; j < 4; j++) {
            float gate = 1.f / (1.f + __expf(-acc[i][j]));
            float a = ast[i][j], b = bst[i][j];
            op[j] = mode ? (gate * b + (1.f - gate) * a)
                         : (gate * a + (1.f - gate) * b);
        }
        *(float4*)(out + (size_t)row * D + tx * 4) = o;
    }
}

__global__ void __launch_bounds__(256, 5)
epilogue(const float* __restrict__ g1, const float* __restrict__ g2,
         const float* __restrict__ g3,
         float* __restrict__ out, float* __restrict__ user_out, int nb0)
{
    int b = blockIdx.x;
    if (b < nb0)
        gate_body(g_eagg, g_iu, g1, g2, out, N_ITEMS, b, 0);
    else
        gate_body(g_ui, g_aagg, g2, g3, user_out, N_USERS, b - nb0, 1);
}

// ---------------- launch -----------------------------------------------------
extern "C" void kernel_launch(void* const* d_in, const int* in_sizes, int n_in,
                              void* d_out, int out_size)
{
    const float* entity_emb = (const float*)d_in[0];
    const float* user_emb   = (const float*)d_in[1];
    const float* weight     = (const float*)d_in[2];
    const float* gate1_w    = (const float*)d_in[3];
    const float* gate2_w    = (const float*)d_in[4];
    const float* gate3_w    = (const float*)d_in[5];
    const int*   edge_index = (const int*)d_in[6];
    const int*   edge_type  = (const int*)d_in[7];
    const int*   uedge_index= (const int*)d_in[8];
    const int*   uedge_type = (const int*)d_in[9];
    const int*   mat_row    = (const int*)d_in[10];
    const int*   mat_col    = (const int*)d_in[11];

    int n_e  = in_sizes[7];    // 1,500,000
    int n_ue = in_sizes[9];    // 1,000,000
    int n_m  = in_sizes[10];   // 1,500,000
    int n_all = n_e + n_ue + 2 * n_m;   // 5,500,000

    float* out = (float*)d_out;
    float* user_out = out + (size_t)N_ENTITIES * D;

    cudaFuncSetAttribute(epilogue, cudaFuncAttributeMaxDynamicSharedMemorySize, GATE_SMEM);

    // 1. fp16 tables + zero degrees
    prep<<<2048, 256>>>((const float4*)entity_emb, (const float4*)user_emb);

    // 2. CSR build
    hist<<<2048, 256>>>(edge_index, n_e, uedge_index, n_ue, mat_row, mat_col, n_m);
    scan1<<<NB_SCAN, 256>>>();
    scan2<<<1, 256>>>();
    scan3<<<NB_SCAN, 256>>>(n_all);
    fill<<<2048, 256>>>(edge_index, edge_index + n_e, edge_type, n_e,
                        uedge_index, uedge_index + n_ue, uedge_type, n_ue,
                        mat_row, mat_col, n_m);

    // 3. gather all four aggregations (atomic-free; writes means + tails)
    gather<<<4736, 256>>>((const float4*)weight, out, user_out);

    // 4. gate epilogue
    int nb0 = (N_ITEMS + 63) / 64;   // 782
    int nb1 = (N_USERS + 63) / 64;   // 1563
    epilogue<<<nb0 + nb1, 256, GATE_SMEM>>>(gate1_w, gate2_w, gate3_w,
                                            out, user_out, nb0);
}

// round 17
// speedup vs baseline: 1.3869x; 1.0074x over previous
#include <cuda_runtime.h>
#include <cuda_fp16.h>
#include <math.h>

#define N_USERS      100000
#define N_ITEMS      50000
#define N_ENTITIES   180000
#define N_USER_NODES 150000
#define N_REL        32
#define D            64
#define DV4          16   // D/4 float4 chunks per row

// virtual destination-row space: [E | A | IU | UI]
#define A_BASE  N_ENTITIES                   // 180000
#define IU_BASE (A_BASE + N_USER_NODES)      // 330000
#define UI_BASE (IU_BASE + N_ITEMS)          // 380000
#define NTOT    (UI_BASE + N_USERS)          // 480000  (= 1875 * 256 exactly)
#define NB_SCAN (NTOT / 256)                 // 1875
#define POST_MAX 6000000

// ---------------- scratch (device globals; no allocation allowed) ----------
__device__ float g_eagg[(size_t)N_ITEMS * D];
__device__ float g_aagg[(size_t)N_USERS * D];
__device__ float g_iu  [(size_t)N_ITEMS * D];
__device__ float g_ui  [(size_t)N_USERS * D];

// fp16 copies of the embedding tables (21MB -> L2 resident)
__device__ uint2 g_eemb_h[(size_t)N_ENTITIES * DV4];
__device__ uint2 g_uemb_h[(size_t)N_USER_NODES * DV4];

// CSR machinery
__device__ int g_deg [NTOT];
__device__ int g_off [NTOT + 1];
__device__ int g_cur [NTOT];
__device__ int g_bsum[NB_SCAN];
__device__ int g_post[POST_MAX];   // posting = src | (type << 20)

typedef unsigned long long u64;

__device__ __forceinline__ uint2 f4_to_h4(float4 v) {
    __half2 lo = __floats2half2_rn(v.x, v.y);
    __half2 hi = __floats2half2_rn(v.z, v.w);
    uint2 o;
    o.x = *reinterpret_cast<unsigned*>(&lo);
    o.y = *reinterpret_cast<unsigned*>(&hi);
    return o;
}

__device__ __forceinline__ float4 h4_to_f4(uint2 p) {
    __half2 lo = *reinterpret_cast<__half2*>(&p.x);
    __half2 hi = *reinterpret_cast<__half2*>(&p.y);
    float2 f0 = __half22float2(lo);
    float2 f1 = __half22float2(hi);
    return make_float4(f0.x, f0.y, f1.x, f1.y);
}

__device__ __forceinline__ u64 pkdup(float a) {
    u64 r; asm("mov.b64 %0, {%1, %1};" : "=l"(r) : "f"(a)); return r;
}
__device__ __forceinline__ void ffma2(u64& d, u64 a, u64 b) {
    asm("fma.rn.f32x2 %0, %1, %2, %0;" : "+l"(d) : "l"(a), "l"(b));
}
__device__ __forceinline__ float2 up2(u64 v) {
    float lo, hi; asm("mov.b64 {%0, %1}, %2;" : "=f"(lo), "=f"(hi) : "l"(v));
    return make_float2(lo, hi);
}

// ---------------- zero degree array (must precede hist) ---------------------
__global__ void zdeg() {
    int i = blockIdx.x * 256 + threadIdx.x;
    int stride = gridDim.x * 256;
    for (; i < NTOT; i += stride) g_deg[i] = 0;
}

// ---------------- fp16 table build || histogram (independent work) ----------
__global__ void conv_hist(const float4* __restrict__ eemb,
                          const float4* __restrict__ uemb,
                          const int* __restrict__ e_head, int n_e,
                          const int* __restrict__ u_head, int n_ue,
                          const int* __restrict__ mrow,
                          const int* __restrict__ mcol, int n_m, int cb)
{
    int b = blockIdx.x;
    if (b < cb) {
        int gid = b * 256 + threadIdx.x;
        int stride = cb * 256;
        const int nE = N_ENTITIES * DV4, nU = N_USER_NODES * DV4;
        for (int i = gid; i < nE; i += stride) g_eemb_h[i] = f4_to_h4(__ldg(eemb + i));
        for (int i = gid; i < nU; i += stride) g_uemb_h[i] = f4_to_h4(__ldg(uemb + i));
    } else {
        int nb = gridDim.x - cb;
        int gid = (b - cb) * 256 + threadIdx.x;
        int stride = nb * 256;
        int n01 = n_e + n_ue, n012 = n01 + n_m, nall = n012 + n_m;
        for (int i = gid; i < nall; i += stride) {
            int dest;
            if      (i < n_e)  dest = __ldcs(e_head + i);
            else if (i < n01)  dest = A_BASE  + __ldcs(u_head + (i - n_e));
            else if (i < n012) dest = IU_BASE + __ldcs(mcol + (i - n01));
            else               dest = UI_BASE + __ldcs(mrow + (i - n012));
            atomicAdd(&g_deg[dest], 1);
        }
    }
}

// ---------------- scan (3 kernels) -------------------------------------------
__global__ void scan1()
{
    __shared__ int s[256];
    int i = blockIdx.x * 256 + threadIdx.x;     // NTOT = 1875*256 exactly
    int v = g_deg[i];
    s[threadIdx.x] = v;
    __syncthreads();
#pragma unroll
    for (int d = 1; d < 256; d <<= 1) {
        int t = (threadIdx.x >= d) ? s[threadIdx.x - d] : 0;
        __syncthreads();
        s[threadIdx.x] += t;
        __syncthreads();
    }
    g_off[i] = s[threadIdx.x] - v;              // exclusive within block
    if (threadIdx.x == 255) g_bsum[blockIdx.x] = s[255];
}

__global__ void scan2()   // single block, warp-shuffle based
{
    __shared__ int wsum[8];
    __shared__ int carry;
    int lane = threadIdx.x & 31, w = threadIdx.x >> 5;
    if (threadIdx.x == 0) carry = 0;
    __syncthreads();
    for (int base = 0; base < NB_SCAN; base += 256) {
        int i = base + threadIdx.x;
        int v = (i < NB_SCAN) ? g_bsum[i] : 0;
        int x = v;
#pragma unroll
        for (int d = 1; d < 32; d <<= 1) {
            int t = __shfl_up_sync(0xffffffff, x, d);
            if (lane >= d) x += t;
        }
        if (lane == 31) wsum[w] = x;
        __syncthreads();
        if (w == 0) {
            int s = (lane < 8) ? wsum[lane] : 0;
#pragma unroll
            for (int d = 1; d < 8; d <<= 1) {
                int t = __shfl_up_sync(0xffffffff, s, d);
                if (lane >= d) s += t;
            }
            if (lane < 8) wsum[lane] = s;       // inclusive warp sums
        }
        __syncthreads();
        int wbase = (w > 0) ? wsum[w - 1] : 0;
        if (i < NB_SCAN) g_bsum[i] = x - v + wbase + carry;
        int tot = wsum[7];
        __syncthreads();
        if (threadIdx.x == 0) carry += tot;
        __syncthreads();
    }
}

__global__ void scan3(int n_all)
{
    int i = blockIdx.x * 256 + threadIdx.x;
    int v = g_off[i] + g_bsum[blockIdx.x];
    g_off[i] = v;
    g_cur[i] = v;
    if (i == 0) g_off[NTOT] = n_all;
}

// ---------------- fill postings ----------------------------------------------
__global__ void fill(const int* __restrict__ e_head, const int* __restrict__ e_tail,
                     const int* __restrict__ e_type, int n_e,
                     const int* __restrict__ u_head, const int* __restrict__ u_tail,
                     const int* __restrict__ u_type, int n_ue,
                     const int* __restrict__ mrow,
                     const int* __restrict__ mcol, int n_m)
{
    int stride = gridDim.x * 256;
    int n01 = n_e + n_ue, n012 = n01 + n_m, nall = n012 + n_m;
    for (int i = blockIdx.x * 256 + threadIdx.x; i < nall; i += stride) {
        int dest, pk;
        if (i < n_e) {
            dest = __ldcs(e_head + i);
            pk   = __ldcs(e_tail + i) | (__ldcs(e_type + i) << 20);
        } else if (i < n01) {
            int j = i - n_e;
            dest = A_BASE + __ldcs(u_head + j);
            pk   = __ldcs(u_tail + j) | (__ldcs(u_type + j) << 20);
        } else if (i < n012) {
            int j = i - n01;
            dest = IU_BASE + __ldcs(mcol + j);
            pk   = __ldcs(mrow + j);                    // type 0 == weight[0]
        } else {
            int j = i - n012;
            dest = UI_BASE + __ldcs(mrow + j);
            pk   = __ldcs(mcol + j);                    // type 0 == weight[0]
        }
        int pos = atomicAdd(&g_cur[dest], 1);
        g_post[pos] = pk;
    }
}

// ---------------- gather (NO atomics) -----------------------------------------
__global__ void __launch_bounds__(256, 8)
gather(const float4* __restrict__ weight,
       float* __restrict__ out, float* __restrict__ user_out)
{
    __shared__ float4 sw[N_REL * DV4];
    for (int i = threadIdx.x; i < N_REL * DV4; i += 256)
        sw[i] = __ldg(weight + i);
    __syncthreads();

    int lane = threadIdx.x & 31;
    int c = lane & 15, half = lane >> 4;
    int warp_id = (blockIdx.x * 256 + threadIdx.x) >> 5;
    int nwarps = (gridDim.x * 256) >> 5;

    for (int vr = warp_id; vr < NTOT; vr += nwarps) {
        int p0 = g_off[vr], p1 = g_off[vr + 1];
        const uint2* tab = (vr < A_BASE)  ? g_eemb_h
                         : (vr < UI_BASE) ? g_uemb_h     // A and IU both gather users
                                          : g_eemb_h;    // UI gathers entities

        float4 acc = make_float4(0.f, 0.f, 0.f, 0.f);
        for (int p = p0 + half; p < p1; p += 2) {
            int e = __ldg((const int*)g_post + p);
            int src = e & 0xFFFFF, ty = e >> 20;
            float4 v = h4_to_f4(__ldg(tab + src * DV4 + c));
            float4 w = sw[ty * DV4 + c];
            acc.x += v.x * w.x; acc.y += v.y * w.y;
            acc.z += v.z * w.z; acc.w += v.w * w.w;
        }
        acc.x += __shfl_xor_sync(0xffffffff, acc.x, 16);
        acc.y += __shfl_xor_sync(0xffffffff, acc.y, 16);
        acc.z += __shfl_xor_sync(0xffffffff, acc.z, 16);
        acc.w += __shfl_xor_sync(0xffffffff, acc.w, 16);

        if (half == 0) {
            float inv = 1.f / fmaxf((float)(p1 - p0), 1.f);
            float4 m = make_float4(acc.x * inv, acc.y * inv, acc.z * inv, acc.w * inv);
            float4* dst;
            if (vr < A_BASE) {
                int r = vr;
                dst = (r < N_ITEMS) ? (float4*)g_eagg + (size_t)r * DV4
                                    : (float4*)out    + (size_t)r * DV4;
            } else if (vr < IU_BASE) {
                int r = vr - A_BASE;
                dst = (r < N_USERS) ? (float4*)g_aagg   + (size_t)r * DV4
                                    : (float4*)user_out + (size_t)r * DV4;
            } else if (vr < UI_BASE) {
                dst = (float4*)g_iu + (size_t)(vr - IU_BASE) * DV4;
            } else {
                dst = (float4*)g_ui + (size_t)(vr - UI_BASE) * DV4;
            }
            dst[c] = m;
        }
    }
}

// ---------------- gated fusion (f32x2 packed mainloop) ------------------------
#define GPAD 68
#define GATE_SMEM ((2 * 64 * GPAD) * 4)

__device__ __forceinline__ void gate_body(
    const float* __restrict__ aggA, const float* __restrict__ aggB,
    const float* __restrict__ GA,   const float* __restrict__ GB,
    float* __restrict__ out, int nrows, int blk, int mode)
{
    extern __shared__ float sm[];
    float* As = sm;                 // [64][GPAD] current-stage operand^T
    float* Gs = sm + 64 * GPAD;     // [64][GPAD] current-stage gate^T

    int tid = threadIdx.x;
    int row0 = blk * 64;
    int tx = tid & 15, ty = tid >> 4;
    const float4* As4 = (const float4*)As;
    const u64* Gs2 = (const u64*)Gs;
    u64 accp[4][2] = {};            // [i][jp]: packed (z_{2jp}, z_{2jp+1})
    float ast[4][4];

    // ---- stage A ----
    for (int idx = tid; idx < 64 * 64; idx += 256) {
        int r = idx >> 6, k = idx & 63;
        int row = row0 + r;
        As[k * GPAD + r] = (row < nrows) ? aggA[(size_t)row * D + k] : 0.f;
    }
    for (int idx = tid; idx < 64 * 64; idx += 256) {
        int j = idx >> 6, k = idx & 63;
        Gs[k * GPAD + j] = __ldg(GA + idx);
    }
    __syncthreads();

#pragma unroll
    for (int j = 0; j < 4; j++) {
        float4 v = As4[(tx * 4 + j) * (GPAD / 4) + ty];
        ast[0][j] = v.x; ast[1][j] = v.y; ast[2][j] = v.z; ast[3][j] = v.w;
    }
#pragma unroll 4
    for (int k = 0; k < 64; k++) {
        float4 av = As4[k * (GPAD / 4) + ty];
        u64 g01 = Gs2[k * (GPAD / 2) + 2 * tx];
        u64 g23 = Gs2[k * (GPAD / 2) + 2 * tx + 1];
        u64 a0 = pkdup(av.x), a1 = pkdup(av.y), a2 = pkdup(av.z), a3 = pkdup(av.w);
        ffma2(accp[0][0], a0, g01); ffma2(accp[0][1], a0, g23);
        ffma2(accp[1][0], a1, g01); ffma2(accp[1][1], a1, g23);
        ffma2(accp[2][0], a2, g01); ffma2(accp[2][1], a2, g23);
        ffma2(accp[3][0], a3, g01); ffma2(accp[3][1], a3, g23);
    }
    __syncthreads();

    // ---- stage B ----
    for (int idx = tid; idx < 64 * 64; idx += 256) {
        int r = idx >> 6, k = idx & 63;
        int row = row0 + r;
        As[k * GPAD + r] = (row < nrows) ? aggB[(size_t)row * D + k] : 0.f;
    }
    for (int idx = tid; idx < 64 * 64; idx += 256) {
        int j = idx >> 6, k = idx & 63;
        Gs[k * GPAD + j] = __ldg(GB + idx);
    }
    __syncthreads();

#pragma unroll 4
    for (int k = 0; k < 64; k++) {
        float4 av = As4[k * (GPAD / 4) + ty];
        u64 g01 = Gs2[k * (GPAD / 2) + 2 * tx];
        u64 g23 = Gs2[k * (GPAD / 2) + 2 * tx + 1];
        u64 a0 = pkdup(av.x), a1 = pkdup(av.y), a2 = pkdup(av.z), a3 = pkdup(av.w);
        ffma2(accp[0][0], a0, g01); ffma2(accp[0][1], a0, g23);
        ffma2(accp[1][0], a1, g01); ffma2(accp[1][1], a1, g23);
        ffma2(accp[2][0], a2, g01); ffma2(accp[2][1], a2, g23);
        ffma2(accp[3][0], a3, g01); ffma2(accp[3][1], a3, g23);
    }

    // ---- blend + store (B still resident in As) ----
    float bst[4][4];
#pragma unroll
    for (int j = 0; j < 4; j++) {
        float4 v = As4[(tx * 4 + j) * (GPAD / 4) + ty];
        bst[0][j] = v.x; bst[1][j] = v.y; bst[2][j] = v.z; bst[3][j] = v.w;
    }
#pragma unroll
    for (int i = 0; i < 4; i++) {
        int r = ty * 4 + i;
        int row = row0 + r;
        if (row >= nrows) continue;
        float2 z01 = up2(accp[i][0]);
        float2 z23 = up2(accp[i][1]);
        float zj[4] = { z01.x, z01.y, z23.x, z23.y };
        float4 o;
        float* op = &o.x;
#pragma unroll
        for (int j = 0; j < 4; j++) {
            float gate = 1.f / (1.f + __expf(-zj[j]));
            float a = ast[i][j], b = bst[i][j];
            op[j] = mode ? (gate * b + (1.f - gate) * a)
                         : (gate * a + (1.f - gate) * b);
        }
        *(float4*)(out + (size_t)row * D + tx * 4) = o;
    }
}

__global__ void __launch_bounds__(256, 5)
epilogue(const float* __restrict__ g1, const float* __restrict__ g2,
         const float* __restrict__ g3,
         float* __restrict__ out, float* __restrict__ user_out, int nb0)
{
    int b = blockIdx.x;
    if (b < nb0)
        gate_body(g_eagg, g_iu, g1, g2, out, N_ITEMS, b, 0);
    else
        gate_body(g_ui, g_aagg, g2, g3, user_out, N_USERS, b - nb0, 1);
}

// ---------------- launch -----------------------------------------------------
extern "C" void kernel_launch(void* const* d_in, const int* in_sizes, int n_in,
                              void* d_out, int out_size)
{
    const float* entity_emb = (const float*)d_in[0];
    const float* user_emb   = (const float*)d_in[1];
    const float* weight     = (const float*)d_in[2];
    const float* gate1_w    = (const float*)d_in[3];
    const float* gate2_w    = (const float*)d_in[4];
    const float* gate3_w    = (const float*)d_in[5];
    const int*   edge_index = (const int*)d_in[6];
    const int*   edge_type  = (const int*)d_in[7];
    const int*   uedge_index= (const int*)d_in[8];
    const int*   uedge_type = (const int*)d_in[9];
    const int*   mat_row    = (const int*)d_in[10];
    const int*   mat_col    = (const int*)d_in[11];

    int n_e  = in_sizes[7];    // 1,500,000
    int n_ue = in_sizes[9];    // 1,000,000
    int n_m  = in_sizes[10];   // 1,500,000
    int n_all = n_e + n_ue + 2 * n_m;   // 5,500,000

    float* out = (float*)d_out;
    float* user_out = out + (size_t)N_ENTITIES * D;

    cudaFuncSetAttribute(epilogue, cudaFuncAttributeMaxDynamicSharedMemorySize, GATE_SMEM);

    // 1. zero degrees, then fp16 tables || histogram (independent)
    zdeg<<<256, 256>>>();
    conv_hist<<<2048, 256>>>((const float4*)entity_emb, (const float4*)user_emb,
                             edge_index, n_e, uedge_index, n_ue,
                             mat_row, mat_col, n_m, 1100);

    // 2. scan + fill
    scan1<<<NB_SCAN, 256>>>();
    scan2<<<1, 256>>>();
    scan3<<<NB_SCAN, 256>>>(n_all);
    fill<<<2048, 256>>>(edge_index, edge_index + n_e, edge_type, n_e,
                        uedge_index, uedge_index + n_ue, uedge_type, n_ue,
                        mat_row, mat_col, n_m);

    // 3. gather all four aggregations (atomic-free; writes means + tails)
    gather<<<4736, 256>>>((const float4*)weight, out, user_out);

    // 4. gate epilogue
    int nb0 = (N_ITEMS + 63) / 64;   // 782
    int nb1 = (N_USERS + 63) / 64;   // 1563
    epilogue<<<nb0 + nb1, 256, GATE_SMEM>>>(gate1_w, gate2_w, gate3_w,
                                            out, user_out, nb0);
}